// round 17
// baseline (speedup 1.0000x reference)
#include <cuda_runtime.h>
#include <cuda_fp16.h>
#include <math.h>
#include <stdint.h>

#define NN 10000
#define TT 128
#define HH 128
#define EE 320000
#define MCTA 80          // nodes per CTA (125 * 80 = 10000 exactly)
#define NCTA 125
#define KT16 9           // K = 144 = 128 (h) + x + 1 + 14 pad, tiles of 16
#define NTH 512          // 16 warps: warp w owns 8 output columns jh in [w*8, w*8+8)

// ---------------- device scratch ----------------
__device__ __align__(16) float g_h1[NN * HH];
__device__ __align__(16) float g_xw[NN * HH];
__device__ __align__(16) float g_h2[NN * HH];
__device__ __align__(16) float g_h3[NN * HH];
__device__ __align__(16) float g_deg[NN];
__device__ __align__(16) float g_dinv[NN];
__device__ __align__(16) float g_norm[EE];
__device__ __align__(16) float g_xT[TT * NN];       // transposed input (raw fp32)
// B fragment order, fp16 halves packed in words: [kt 9][w 16][gt 4][lane 32][reg 2]
__device__ __align__(16) uint32_t g_Bhi[KT16 * 4096];
__device__ __align__(16) uint32_t g_Blo[KT16 * 4096];

// ---------------- helpers ----------------
__device__ __forceinline__ uint32_t smem_u32(const void* p) {
    uint32_t a;
    asm("{ .reg .u64 t; cvta.to.shared.u64 t, %1; cvt.u32.u64 %0, t; }" : "=r"(a) : "l"(p));
    return a;
}
// 1-MUFU nonlinearities (tanh.approx, sm_75+)
__device__ __forceinline__ float tanha(float x) {
    float r; asm("tanh.approx.f32 %0, %1;" : "=f"(r) : "f"(x)); return r;
}
__device__ __forceinline__ float siga(float x) {
    return fmaf(0.5f, tanha(0.5f * x), 0.5f);
}
// pack two fp32 -> half2 word (lo half = first arg = even-k element)
__device__ __forceinline__ uint32_t pack_h2(float a, float b) {
    uint32_t r;
    asm("{\n\t.reg .f16 l, h;\n\tcvt.rn.f16.f32 l, %1;\n\tcvt.rn.f16.f32 h, %2;\n\t"
        "mov.b32 %0, {l, h};\n\t}" : "=r"(r) : "f"(a), "f"(b));
    return r;
}
__device__ __forceinline__ void mma_f16(float& d0, float& d1, float& d2, float& d3,
                                        uint32_t a0, uint32_t a1, uint32_t a2, uint32_t a3,
                                        uint32_t b0, uint32_t b1) {
    asm volatile("mma.sync.aligned.m16n8k16.row.col.f32.f16.f16.f32 "
                 "{%0,%1,%2,%3}, {%4,%5,%6,%7}, {%8,%9}, {%0,%1,%2,%3};"
                 : "+f"(d0), "+f"(d1), "+f"(d2), "+f"(d3)
                 : "r"(a0), "r"(a1), "r"(a2), "r"(a3), "r"(b0), "r"(b1));
}
// ORDERED shared loads (R10 fix: never hoisted across cp.async waits / stores)
#define LDSV4(r0, r1, r2, r3, addr) \
    asm volatile("ld.shared.v4.b32 {%0,%1,%2,%3}, [%4];" \
        : "=r"(r0), "=r"(r1), "=r"(r2), "=r"(r3) : "r"(addr) : "memory")
#define LDSV2(r0, r1, addr) \
    asm volatile("ld.shared.v2.b32 {%0,%1}, [%2];" \
        : "=r"(r0), "=r"(r1) : "r"(addr) : "memory")

// ---------------- prep: B fragment-order, fp16 hi + lo ----------------
// D column d = gt*128 + jh. Warp w = jh>>3 owns 8 columns; gate tile = gt (0..3).
// B frag (m16n8k16 col-major): (k, n=jh&7):
//   lane = (jh&7)*4 + ((kk&7)>>1), reg = kk>>3, khalf = kk&1, kt = k>>4.
// B rows: k<128: Whh[d][k]; k=128: Wih[d]; k=129: bih[d]+bhh[d]; else 0.
__global__ void prep_tc(const float* __restrict__ Whh, const float* __restrict__ Wih,
                        const float* __restrict__ bih, const float* __restrict__ bhh) {
    int idx = blockIdx.x * blockDim.x + threadIdx.x;
    if (idx >= 512 * 144) return;
    int d = idx / 144, k = idx % 144;
    float v;
    if (k < 128)       v = Whh[d * 128 + k];
    else if (k == 128) v = Wih[d];
    else if (k == 129) v = bih[d] + bhh[d];
    else               v = 0.0f;
    __half hi = __float2half_rn(v);
    float lo = v - __half2float(hi);
    __half lo_h = __float2half_rn(lo);
    int gt = d >> 7, jh = d & 127;
    int w = jh >> 3, nlo = jh & 7;
    int kt = k >> 4, kk = k & 15;
    int lane = nlo * 4 + ((kk & 7) >> 1);
    int reg = kk >> 3, khalf = kk & 1;
    int hidx = (((((kt * 16) + w) * 4 + gt) * 32 + lane) * 2 + reg) * 2 + khalf;
    ((__half*)g_Bhi)[hidx] = hi;
    ((__half*)g_Blo)[hidx] = lo_h;
}

// tiled transpose: x[n][t] -> g_xT[t][n], both sides coalesced
__global__ void xt_k(const float* __restrict__ x) {
    __shared__ float tile[32][33];
    int nb = blockIdx.x * 32;
    int tb = blockIdx.y * 32;
    int lx = threadIdx.x & 31;
    int ly4 = threadIdx.x >> 5;
#pragma unroll
    for (int rr = 0; rr < 4; rr++) {
        int n = nb + ly4 * 4 + rr;
        if (n < NN) tile[ly4 * 4 + rr][lx] = x[n * TT + tb + lx];
    }
    __syncthreads();
#pragma unroll
    for (int rr = 0; rr < 4; rr++) {
        int n = nb + lx;
        if (n < NN) g_xT[(tb + ly4 * 4 + rr) * NN + n] = tile[lx][ly4 * 4 + rr];
    }
}

// ---------------- LSTM: 2-term fp16 mma, 16 warps, cyclic 3-stage B pipeline ------
// smem words: AH 5760 | BH 3x4096 | BL 3x4096 | CC 512*21 (floats)
#define AH_F   0
#define BH_F   5760
#define BL_F   18048
#define CC_F   30336
#define SMF    (30336 + 512 * 21)
#define SM_BYTES (SMF * 4)

// prefetch one k-tile (warp's hi + lo slices, 1KB each) into buffer bf
#define PREFETCH_TILE(tile, bf) do { \
    _Pragma("unroll") \
    for (int rr = 0; rr < 2; rr++) { \
        uint32_t dh = sa + (uint32_t)((BH_F + (bf) * 4096 + w * 256 + lane * 4 + rr * 128) * 4); \
        const uint32_t* sh = g_Bhi + ((tile) * 4096 + w * 256 + lane * 4 + rr * 128); \
        asm volatile("cp.async.cg.shared.global [%0], [%1], 16;" :: "r"(dh), "l"(sh)); \
        uint32_t dl = sa + (uint32_t)((BL_F + (bf) * 4096 + w * 256 + lane * 4 + rr * 128) * 4); \
        const uint32_t* sl = g_Blo + ((tile) * 4096 + w * 256 + lane * 4 + rr * 128); \
        asm volatile("cp.async.cg.shared.global [%0], [%1], 16;" :: "r"(dl), "l"(sl)); \
    } \
    asm volatile("cp.async.commit_group;" ::: "memory"); \
} while (0)

__global__ __launch_bounds__(NTH, 1) void lstm_tc() {
    extern __shared__ __align__(16) float sm[];
    uint32_t* smw = (uint32_t*)sm;
    uint32_t sa = smem_u32(sm);
    int tid = threadIdx.x;
    int w = tid >> 5;           // warp id 0..15 = 8-column slice
    int lane = tid & 31;
    int nbase = blockIdx.x * MCTA;

    // zero all smem (A plane, all B buffers, c)
    for (int i = tid; i < SMF; i += NTH) sm[i] = 0.0f;
    __syncthreads();
    // x0 + ones packed word at kt=8, kk=0/1 (same word: half2(x, 1))
    if (tid < MCTA) {
        int n = tid, mt = n >> 4, r = n & 15;
        int lane0 = ((r & 7) << 2), reg0 = r >> 3;
        float xv = g_xT[0 * NN + nbase + n];
        smw[((mt * KT16 + 8) * 32 + lane0) * 4 + reg0] = pack_h2(xv, 1.0f);
    }
    __syncthreads();

    // pipeline prologue: tiles 0 and 1 in flight (buffers 0, 1)
    PREFETCH_TILE(0, 0);
    PREFETCH_TILE(1, 1);

    for (int t = 0; t < TT; t++) {
        float acc[4][5][4];
#pragma unroll
        for (int gt = 0; gt < 4; gt++)
#pragma unroll
            for (int mt = 0; mt < 5; mt++)
#pragma unroll
                for (int q = 0; q < 4; q++) acc[gt][mt][q] = 0.0f;

#pragma unroll
        for (int kt = 0; kt < KT16; kt++) {
            // cyclic prefetch: tile (kt+2) mod 9 -> buffer (kt+2) mod 3.
            // B is time-invariant; pipeline runs across step boundaries.
            PREFETCH_TILE((kt + 2) % KT16, (kt + 2) % 3);
            asm volatile("cp.async.wait_group 2;" ::: "memory");
            __syncwarp();

            // B fragments (hi + lo) — ordered loads, cached for this k-tile
            uint32_t bh[4][2], bl[4][2];
            uint32_t bhib = sa + (uint32_t)((BH_F + (kt % 3) * 4096 + w * 256) * 4);
            uint32_t blob = sa + (uint32_t)((BL_F + (kt % 3) * 4096 + w * 256) * 4);
#pragma unroll
            for (int gt = 0; gt < 4; gt++) {
                LDSV2(bh[gt][0], bh[gt][1], bhib + (uint32_t)((gt * 32 + lane) * 8));
                LDSV2(bl[gt][0], bl[gt][1], blob + (uint32_t)((gt * 32 + lane) * 8));
            }
            // A frags streamed; 2 MMAs per (mt, gt)
#pragma unroll
            for (int mt = 0; mt < 5; mt++) {
                uint32_t a0, a1, a2, a3;
                uint32_t aaddr = sa + (uint32_t)((((mt * KT16 + kt) * 32 + lane) * 4) * 4);
                LDSV4(a0, a1, a2, a3, aaddr);
#pragma unroll
                for (int gt = 0; gt < 4; gt++) {
                    mma_f16(acc[gt][mt][0], acc[gt][mt][1], acc[gt][mt][2], acc[gt][mt][3],
                            a0, a1, a2, a3, bh[gt][0], bh[gt][1]);
                    mma_f16(acc[gt][mt][0], acc[gt][mt][1], acc[gt][mt][2], acc[gt][mt][3],
                            a0, a1, a2, a3, bl[gt][0], bl[gt][1]);
                }
            }
        }
        __syncthreads();   // all A reads done before epilogue overwrites A

        // epilogue: cell update; c in smem (stride 21, conflict-free)
#pragma unroll
        for (int mt = 0; mt < 5; mt++) {
#pragma unroll
            for (int rh = 0; rh < 2; rh++) {
                int r = (lane >> 2) + rh * 8;
                int n = mt * 16 + r;
                float hv[2];
#pragma unroll
                for (int nlo = 0; nlo < 2; nlo++) {
                    int ci = (mt * 2 + rh) * 2 + nlo;
                    int q = rh * 2 + nlo;
                    float pi = acc[0][mt][q];
                    float pf = acc[1][mt][q];
                    float pg = acc[2][mt][q];
                    float po = acc[3][mt][q];
                    float cold = sm[CC_F + tid * 21 + ci];
                    float cn = siga(pf) * cold + siga(pi) * tanha(pg);
                    sm[CC_F + tid * 21 + ci] = cn;
                    float h = siga(po) * tanha(cn);
                    hv[nlo] = h;
                    if (t == TT - 1 && nbase + n < NN) {
                        int jh = w * 8 + ((lane & 3) << 1) + nlo;
                        g_h1[(nbase + n) * HH + jh] = fmaxf(h, 0.0f);
                    }
                }
                // store packed h pair: jh = w*8 + (lane&3)*2 + {0,1}
                // kl = jh & 15 -> col-half (w&1), kt tile = w >> 1
                int lane2 = ((r & 7) << 2) + (lane & 3);
                int reg2 = (r >> 3) + ((w & 1) << 1);
                smw[((mt * KT16 + (w >> 1)) * 32 + lane2) * 4 + reg2] = pack_h2(hv[0], hv[1]);
            }
        }
        // x + ones word for next step
        if (t < TT - 1 && tid < MCTA) {
            int n = tid, mt = n >> 4, r = n & 15;
            int lane0 = ((r & 7) << 2), reg0 = r >> 3;
            float xv = g_xT[(t + 1) * NN + nbase + n];
            smw[((mt * KT16 + 8) * 32 + lane0) * 4 + reg0] = pack_h2(xv, 1.0f);
        }
        __syncthreads();
    }
}

// ---------------- GCN dense GEMM, fused (bias-relu in, self-loop out) ------------
__global__ __launch_bounds__(256) void gemm_k(const float* __restrict__ X,
                                              const float* __restrict__ W,
                                              float* __restrict__ Y,
                                              float* __restrict__ Ydst,
                                              const float* __restrict__ bias, int N) {
    __shared__ __align__(16) float Xs[32][128];
    __shared__ __align__(16) float Ws[64][128];
    int tid = threadIdx.x;
    int node = tid >> 3;
    int jq = tid & 7;
    int j0 = jq * 16;
    int nb = blockIdx.x * 32;

    for (int idx = tid; idx < 32 * 128; idx += 256) {
        int n = idx >> 7, k = idx & 127;
        float xv = (nb + n < N) ? X[(nb + n) * 128 + k] : 0.f;
        if (bias) xv = fmaxf(xv + bias[k], 0.f);
        Xs[n][k] = xv;
    }
    float4 a0 = make_float4(0.f, 0.f, 0.f, 0.f), a1 = a0, a2 = a0, a3 = a0;

    for (int half = 0; half < 2; half++) {
        __syncthreads();
        for (int idx = tid; idx < 64 * 128; idx += 256) {
            int k = idx >> 7, j = idx & 127;
            Ws[k][j] = W[(half * 64 + k) * 128 + j];
        }
        __syncthreads();
#pragma unroll 8
        for (int k8 = 0; k8 < 64; k8++) {
            float xv = Xs[node][half * 64 + k8];
            const float4* wr = (const float4*)&Ws[k8][j0];
            float4 w0 = wr[0], w1 = wr[1], w2 = wr[2], w3 = wr[3];
            a0.x += xv * w0.x; a0.y += xv * w0.y; a0.z += xv * w0.z; a0.w += xv * w0.w;
            a1.x += xv * w1.x; a1.y += xv * w1.y; a1.z += xv * w1.z; a1.w += xv * w1.w;
            a2.x += xv * w2.x; a2.y += xv * w2.y; a2.z += xv * w2.z; a2.w += xv * w2.w;
            a3.x += xv * w3.x; a3.y += xv * w3.y; a3.z += xv * w3.z; a3.w += xv * w3.w;
        }
    }
    if (nb + node < N) {
        float4* yo = (float4*)&Y[(nb + node) * 128 + j0];
        yo[0] = a0; yo[1] = a1; yo[2] = a2; yo[3] = a3;
        float dv = g_dinv[nb + node];
        float s = dv * dv;
        float4 b0 = make_float4(a0.x * s, a0.y * s, a0.z * s, a0.w * s);
        float4 b1v = make_float4(a1.x * s, a1.y * s, a1.z * s, a1.w * s);
        float4 b2v = make_float4(a2.x * s, a2.y * s, a2.z * s, a2.w * s);
        float4 b3v = make_float4(a3.x * s, a3.y * s, a3.z * s, a3.w * s);
        float4* yd = (float4*)&Ydst[(nb + node) * 128 + j0];
        yd[0] = b0; yd[1] = b1v; yd[2] = b2v; yd[3] = b3v;
    }
}

// ---------------- graph normalization + scatter ----------------
__global__ void deg_init(int N) {
    int i = blockIdx.x * blockDim.x + threadIdx.x;
    if (i < N) g_deg[i] = 1.0f;
}
__global__ void deg_scatter(const int* __restrict__ col, const float* __restrict__ ew, int E) {
    int e = blockIdx.x * blockDim.x + threadIdx.x;
    if (e < E) atomicAdd(&g_deg[col[e]], ew[e]);
}
__global__ void dinv_k(int N) {
    int i = blockIdx.x * blockDim.x + threadIdx.x;
    if (i < N) g_dinv[i] = rsqrtf(g_deg[i]);
}
__global__ void norm_k(const int* __restrict__ row, const int* __restrict__ col,
                       const float* __restrict__ ew, int E) {
    int e = blockIdx.x * blockDim.x + threadIdx.x;
    if (e < E) g_norm[e] = g_dinv[row[e]] * ew[e] * g_dinv[col[e]];
}
// warp per edge: dst[col] += norm[e] * src[row], one red.v4 per lane
__global__ void scatter_k(const float* __restrict__ src, float* __restrict__ dst,
                          const int* __restrict__ row, const int* __restrict__ col, int E) {
    int gid = blockIdx.x * blockDim.x + threadIdx.x;
    int e = gid >> 5;
    if (e >= E) return;
    int lane = gid & 31;
    int r = row[e], cc = col[e];
    float nv = g_norm[e];
    float4 v = ((const float4*)(src + r * 128))[lane];
    float* d = dst + cc * 128 + lane * 4;
    asm volatile("red.global.add.v4.f32 [%0], {%1, %2, %3, %4};"
                 :: "l"(d), "f"(nv * v.x), "f"(nv * v.y), "f"(nv * v.z), "f"(nv * v.w)
                 : "memory");
}
__global__ void pool_k(const float* __restrict__ h, const float* __restrict__ b2,
                       float* __restrict__ out, int N) {
    int f = blockIdx.x;
    float s = 0.f;
    for (int n = threadIdx.x; n < N; n += blockDim.x) s += h[n * 128 + f];
    __shared__ float red[256];
    red[threadIdx.x] = s;
    __syncthreads();
    for (int o = 128; o > 0; o >>= 1) {
        if (threadIdx.x < o) red[threadIdx.x] += red[threadIdx.x + o];
        __syncthreads();
    }
    if (threadIdx.x == 0) out[f] = red[0] / (float)N + b2[f];
}

// ---------------- launch ----------------
extern "C" void kernel_launch(void* const* d_in, const int* in_sizes, int n_in,
                              void* d_out, int out_size) {
    const float* x   = (const float*)d_in[0];
    const int*   ei  = (const int*)d_in[1];
    const float* ew  = (const float*)d_in[2];
    const float* Wih = (const float*)d_in[3];
    const float* Whh = (const float*)d_in[4];
    const float* bih = (const float*)d_in[5];
    const float* bhh = (const float*)d_in[6];
    const float* W1  = (const float*)d_in[7];
    const float* b1  = (const float*)d_in[8];
    const float* W2  = (const float*)d_in[9];
    const float* b2  = (const float*)d_in[10];
    float* out = (float*)d_out;

    int N = in_sizes[0] / TT;
    int E = in_sizes[2];
    const int* row = ei;
    const int* col = ei + E;

    float *p_h1, *p_xw, *p_h2, *p_h3;
    cudaGetSymbolAddress((void**)&p_h1, g_h1);
    cudaGetSymbolAddress((void**)&p_xw, g_xw);
    cudaGetSymbolAddress((void**)&p_h2, g_h2);
    cudaGetSymbolAddress((void**)&p_h3, g_h3);

    cudaFuncSetAttribute(lstm_tc, cudaFuncAttributeMaxDynamicSharedMemorySize, SM_BYTES);

    int nb256 = (N + 255) / 256;
    int eb256 = (E + 255) / 256;

    prep_tc<<<(512 * 144 + 255) / 256, 256>>>(Whh, Wih, bih, bhh);
    {
        dim3 tg((NN + 31) / 32, TT / 32);
        xt_k<<<tg, 256>>>(x);
    }
    lstm_tc<<<NCTA, NTH, SM_BYTES>>>();                // 125 CTAs x 512 thr -> g_h1

    deg_init<<<nb256, 256>>>(N);
    deg_scatter<<<eb256, 256>>>(col, ew, E);
    dinv_k<<<nb256, 256>>>(N);
    norm_k<<<eb256, 256>>>(row, col, ew, E);

    // GCN layer 1: gemm writes xw (unscaled) + h2 = dinv^2 * xw
    gemm_k<<<(N + 31) / 32, 256>>>(p_h1, W1, p_xw, p_h2, nullptr, N);
    scatter_k<<<(E * 32 + 255) / 256, 256>>>(p_xw, p_h2, row, col, E);

    // GCN layer 2: operand = relu(h2 + b1) fused into load
    gemm_k<<<(N + 31) / 32, 256>>>(p_h2, W2, p_xw, p_h3, b1, N);
    scatter_k<<<(E * 32 + 255) / 256, 256>>>(p_xw, p_h3, row, col, E);

    pool_k<<<128, 256>>>(p_h3, b2, out, N);
}